// round 2
// baseline (speedup 1.0000x reference)
#include <cuda_runtime.h>

// Problem constants
#define N1    192
#define N2    48
#define D_IN  1024
#define D1    1025          // D_IN + 1 (bias row)
#define D_OUT 512
#define LAM   0.001f
#define LR    0.01f
#define ITRS  100

#define NCH   16            // d-dimension chunks for the reduction pass
#define DPC   65            // ceil(1025/16)

// Deterministic scratch (no device-side allocation allowed)
__device__ float g_pA[NCH * N2 * N1];   // partial raw A (pre-normalization)
__device__ float g_pQ[NCH * N2 * N1];   // partial q = h1^T W0
__device__ float g_pS[NCH * N2];        // partial s0 = ||W0||_F^2
__device__ float g_beta[N2];
__device__ float g_u[N2 * N1];

// ---------------------------------------------------------------------------
// Pass 1: stream We + W0 once, producing per-(chunk,group) partials.
// Block = (group n, chunk c), 192 threads (one per column k). Reads are fully
// coalesced (k is the contiguous dim). 48*16 = 768 blocks saturate HBM.
// ---------------------------------------------------------------------------
__global__ void __launch_bounds__(N1) reduce_kernel(
    const float* __restrict__ x,
    const float* __restrict__ We,
    const float* __restrict__ W0)
{
    const int n = blockIdx.x;
    const int c = blockIdx.y;
    const int k = threadIdx.x;
    const int d0 = c * DPC;
    const int d1 = (d0 + DPC < D1) ? (d0 + DPC) : D1;

    const float* we = We + (size_t)n * D1 * N1 + (size_t)d0 * N1 + k;
    const float* w0 = W0 + (size_t)n * D1 * N1 + (size_t)d0 * N1 + k;

    float a = 0.f, q = 0.f, s = 0.f;
    for (int d = d0; d < d1; ++d) {
        float h  = (d < D_IN) ? __ldg(x + d) : 1.0f;   // h1[d]
        float wv = __ldg(we);  we += N1;
        float w0v = __ldg(w0); w0 += N1;
        a = fmaf(h, wv, a);
        q = fmaf(h, w0v, q);
        s = fmaf(w0v, w0v, s);
    }
    g_pA[(c * N2 + n) * N1 + k] = a;
    g_pQ[(c * N2 + n) * N1 + k] = q;

    // block-reduce s (192 threads = 6 warps)
    __shared__ float sm[6];
    #pragma unroll
    for (int o = 16; o > 0; o >>= 1) s += __shfl_down_sync(0xffffffffu, s, o);
    if ((k & 31) == 0) sm[k >> 5] = s;
    __syncthreads();
    if (k == 0) {
        float t = 0.f;
        #pragma unroll
        for (int i = 0; i < 6; ++i) t += sm[i];
        g_pS[c * N2 + n] = t;
    }
}

// ---------------------------------------------------------------------------
// Pass 2: per-group 100-step GD in the collapsed (beta, u) representation.
// 48 blocks x 192 threads. One fused 2-value block reduction per iteration.
// ---------------------------------------------------------------------------
__global__ void __launch_bounds__(N1) iter_kernel(const float* __restrict__ x)
{
    const int n = blockIdx.x;
    const int k = threadIdx.x;

    // Deterministic gather of partials
    float A = 0.f, q = 0.f;
    #pragma unroll
    for (int c = 0; c < NCH; ++c) {
        A += g_pA[(c * N2 + n) * N1 + k];
        q += g_pQ[(c * N2 + n) * N1 + k];
    }
    float s0 = 0.f;
    #pragma unroll
    for (int c = 0; c < NCH; ++c) s0 += g_pS[c * N2 + n];

    // hh = ||h1||^2 = sum x^2 + 1  (computed redundantly per block; trivial)
    float hp = 0.f;
    for (int i = k; i < D_IN; i += N1) { float v = x[i]; hp = fmaf(v, v, hp); }

    __shared__ float sm[12];
    __shared__ float bc[3];

    // Fused reduction: ||A_raw||^2 and sum x^2
    float aa = A * A;
    float h2 = hp;
    #pragma unroll
    for (int o = 16; o > 0; o >>= 1) {
        aa += __shfl_down_sync(0xffffffffu, aa, o);
        h2 += __shfl_down_sync(0xffffffffu, h2, o);
    }
    if ((k & 31) == 0) { sm[k >> 5] = aa; sm[6 + (k >> 5)] = h2; }
    __syncthreads();
    if (k == 0) {
        float ta = 0.f, th = 0.f;
        #pragma unroll
        for (int i = 0; i < 6; ++i) { ta += sm[i]; th += sm[6 + i]; }
        bc[0] = 1.0f / sqrtf(ta);   // 1/||A_raw||
        bc[1] = th + 1.0f;          // hh
    }
    __syncthreads();
    const float invNa = bc[0];
    const float hh    = bc[1];
    A *= invNa;                      // normalized A (F.normalize p=2 dim=-1)

    float u = 0.f;
    float beta = 1.0f;

    for (int t = 0; t < ITRS; ++t) {
        // dot1 = q.u, dot2 = u.u  (fused block reduction)
        float d1v = q * u, d2v = u * u;
        #pragma unroll
        for (int o = 16; o > 0; o >>= 1) {
            d1v += __shfl_down_sync(0xffffffffu, d1v, o);
            d2v += __shfl_down_sync(0xffffffffu, d2v, o);
        }
        if ((k & 31) == 0) { sm[k >> 5] = d1v; sm[6 + (k >> 5)] = d2v; }
        __syncthreads();
        if (k == 0) {
            float t1 = 0.f, t2 = 0.f;
            #pragma unroll
            for (int i = 0; i < 6; ++i) { t1 += sm[i]; t2 += sm[6 + i]; }
            float nw = sqrtf(beta * beta * s0 + 2.0f * beta * t1 + hh * t2);
            bc[2] = 1.0f - (LR * LAM) / nw;   // alpha_t
        }
        __syncthreads();
        const float alpha = bc[2];
        const float r = beta * q + hh * u - A;     // r_t[k]
        u = alpha * u - (2.0f * LR) * r;
        beta = alpha * beta;
        __syncthreads();   // protect sm/bc reuse next iteration
    }

    g_u[n * N1 + k] = u;
    if (k == 0) g_beta[n] = beta;
}

// ---------------------------------------------------------------------------
// Pass 3: W_all = beta_n * W0 + h1 * u^T, float4-vectorized streaming write.
// ---------------------------------------------------------------------------
__global__ void __launch_bounds__(256) out_kernel(
    const float* __restrict__ x,
    const float* __restrict__ W0,
    float* __restrict__ out)   // points at d_out + 512
{
    const int K4 = N1 / 4;                               // 48
    const size_t total = (size_t)N2 * D1 * K4;           // 2,361,600
    size_t idx = (size_t)blockIdx.x * blockDim.x + threadIdx.x;
    if (idx >= total) return;

    int k4 = (int)(idx % K4);
    size_t t = idx / K4;
    int d = (int)(t % D1);
    int n = (int)(t / D1);

    float4 w  = ((const float4*)W0)[idx];
    float4 uv = ((const float4*)g_u)[n * K4 + k4];
    float  h  = (d < D_IN) ? __ldg(x + d) : 1.0f;
    float  b  = g_beta[n];

    float4 o;
    o.x = fmaf(b, w.x, h * uv.x);
    o.y = fmaf(b, w.y, h * uv.y);
    o.z = fmaf(b, w.z, h * uv.z);
    o.w = fmaf(b, w.w, h * uv.w);
    ((float4*)out)[idx] = o;
}

// ---------------------------------------------------------------------------
// pred = x @ Wp^T + bp  (one warp per output row, coalesced)
// ---------------------------------------------------------------------------
__global__ void __launch_bounds__(128) pred_kernel(
    const float* __restrict__ x,
    const float* __restrict__ Wp,
    const float* __restrict__ bp,
    float* __restrict__ out)
{
    int warp = (blockIdx.x * blockDim.x + threadIdx.x) >> 5;
    int lane = threadIdx.x & 31;
    if (warp >= D_OUT) return;
    const float* row = Wp + (size_t)warp * D_IN;
    float s = 0.f;
    for (int i = lane; i < D_IN; i += 32) s = fmaf(row[i], x[i], s);
    #pragma unroll
    for (int o = 16; o > 0; o >>= 1) s += __shfl_down_sync(0xffffffffu, s, o);
    if (lane == 0) out[warp] = s + bp[warp];
}

// ---------------------------------------------------------------------------
extern "C" void kernel_launch(void* const* d_in, const int* in_sizes, int n_in,
                              void* d_out, int out_size)
{
    const float* x  = (const float*)d_in[0];
    const float* We = (const float*)d_in[1];
    const float* W0 = (const float*)d_in[2];
    const float* Wp = (const float*)d_in[3];
    const float* bp = (const float*)d_in[4];
    float* out = (float*)d_out;

    // Pass 1: stream We + W0 -> partial A, q, s0
    reduce_kernel<<<dim3(N2, NCH), N1>>>(x, We, W0);

    // Pass 2: collapsed GD iterations -> beta, u
    iter_kernel<<<N2, N1>>>(x);

    // Pass 3: write W_all (after the 512 pred floats)
    {
        const size_t total4 = (size_t)N2 * D1 * (N1 / 4);
        int grid = (int)((total4 + 255) / 256);
        out_kernel<<<grid, 256>>>(x, W0, out + D_OUT);
    }

    // pred (independent; serialized on default stream, trivial cost)
    pred_kernel<<<(D_OUT * 32 + 127) / 128, 128>>>(x, Wp, bp, out);
}

// round 3
// speedup vs baseline: 2.4091x; 2.4091x over previous
#include <cuda_runtime.h>

// Problem constants
#define N1    192
#define N2    48
#define D_IN  1024
#define D1    1025          // D_IN + 1 (bias row)
#define D_OUT 512
#define LAM   0.001f
#define LR    0.01f
#define ITRS  100

#define NCH   16            // d-dimension chunks for the reduction pass
#define DPC   65            // ceil(1025/16)
#define K4    (N1/4)        // 48 float4 columns

#define NB_RED  (N2*NCH)    // 768 reduce blocks
#define NB_PRED 64          // 64 pred blocks (8 warps x 64 = 512 rows)

// Deterministic scratch (no device-side allocation allowed)
__device__ float4 g_pA4[NCH * N2 * K4];   // partial raw A (pre-normalization)
__device__ float4 g_pQ4[NCH * N2 * K4];   // partial q = h1^T W0
__device__ float  g_pS [NCH * N2];        // partial s0 = ||W0||_F^2
__device__ float  g_beta[N2];
__device__ float4 g_u4 [N2 * K4];

// ---------------------------------------------------------------------------
// Pass A (fused): reduce partials over We/W0  +  pred = x@Wp^T + bp.
// Reduce blocks: (group n, chunk c), 240 active threads as (k4:48, dr:5),
// float4 loads, fully coalesced (48 threads cover a contiguous 768B row).
// Pred blocks: one warp per output row, float4 loads, 8-deep MLP.
// ---------------------------------------------------------------------------
__global__ void __launch_bounds__(256) fusedA_kernel(
    const float* __restrict__ x,
    const float* __restrict__ We,
    const float* __restrict__ W0,
    const float* __restrict__ Wp,
    const float* __restrict__ bp,
    float* __restrict__ out)
{
    if (blockIdx.x < NB_RED) {
        const int n = blockIdx.x % N2;
        const int c = blockIdx.x / N2;
        const int t = threadIdx.x;

        __shared__ float4 smA[5][K4];
        __shared__ float4 smQ[5][K4];
        __shared__ float  smS[8];

        float s = 0.f;
        if (t < 240) {
            const int k4 = t % K4;
            const int dr = t / K4;           // 0..4
            const int d0 = c * DPC;
            const int dEnd = (d0 + DPC < D1) ? (d0 + DPC) : D1;

            float4 a4 = make_float4(0.f, 0.f, 0.f, 0.f);
            float4 q4 = make_float4(0.f, 0.f, 0.f, 0.f);

            const float4* we4 = (const float4*)We;
            const float4* w04 = (const float4*)W0;
            const size_t gbase = (size_t)n * D1 * K4 + k4;

            for (int d = d0 + dr; d < dEnd; d += 5) {
                float  h  = (d < D_IN) ? __ldg(x + d) : 1.0f;
                float4 wv = __ldg(we4 + gbase + (size_t)d * K4);
                float4 w0 = __ldg(w04 + gbase + (size_t)d * K4);
                a4.x = fmaf(h, wv.x, a4.x); a4.y = fmaf(h, wv.y, a4.y);
                a4.z = fmaf(h, wv.z, a4.z); a4.w = fmaf(h, wv.w, a4.w);
                q4.x = fmaf(h, w0.x, q4.x); q4.y = fmaf(h, w0.y, q4.y);
                q4.z = fmaf(h, w0.z, q4.z); q4.w = fmaf(h, w0.w, q4.w);
                s = fmaf(w0.x, w0.x, s); s = fmaf(w0.y, w0.y, s);
                s = fmaf(w0.z, w0.z, s); s = fmaf(w0.w, w0.w, s);
            }
            smA[dr][k4] = a4;
            smQ[dr][k4] = q4;
        }

        // block-reduce s (8 warps; idle threads carry 0)
        #pragma unroll
        for (int o = 16; o > 0; o >>= 1) s += __shfl_down_sync(0xffffffffu, s, o);
        if ((t & 31) == 0) smS[t >> 5] = s;
        __syncthreads();

        if (t < K4) {
            float4 a4 = smA[0][t], q4 = smQ[0][t];
            #pragma unroll
            for (int r = 1; r < 5; ++r) {
                float4 a = smA[r][t], q = smQ[r][t];
                a4.x += a.x; a4.y += a.y; a4.z += a.z; a4.w += a.w;
                q4.x += q.x; q4.y += q.y; q4.z += q.z; q4.w += q.w;
            }
            g_pA4[(c * N2 + n) * K4 + t] = a4;
            g_pQ4[(c * N2 + n) * K4 + t] = q4;
        }
        if (t == 0) {
            float tot = 0.f;
            #pragma unroll
            for (int i = 0; i < 8; ++i) tot += smS[i];
            g_pS[c * N2 + n] = tot;
        }
    } else {
        // --- pred role: one warp per output row, float4, unrolled ---
        const int warp = (blockIdx.x - NB_RED) * 8 + (threadIdx.x >> 5);
        const int lane = threadIdx.x & 31;
        const float4* row = (const float4*)(Wp + (size_t)warp * D_IN);
        const float4* x4  = (const float4*)x;
        float sacc = 0.f;
        #pragma unroll
        for (int i = 0; i < 8; ++i) {
            float4 w = __ldg(row + lane + i * 32);
            float4 v = __ldg(x4  + lane + i * 32);
            sacc = fmaf(w.x, v.x, sacc); sacc = fmaf(w.y, v.y, sacc);
            sacc = fmaf(w.z, v.z, sacc); sacc = fmaf(w.w, v.w, sacc);
        }
        #pragma unroll
        for (int o = 16; o > 0; o >>= 1) sacc += __shfl_down_sync(0xffffffffu, sacc, o);
        if (lane == 0) out[warp] = sacc + __ldg(bp + warp);
    }
}

// ---------------------------------------------------------------------------
// Pass B: finalize scalars + fully-collapsed GD.
// u_t = p_t * q + a_t * Ahat  (exact span collapse), so the 100 iterations
// are scalar recurrences on (p, a, beta). One fused 5-value block reduction,
// then thread 0 iterates, then all threads emit u = p*q + (a/||A||)*A_raw.
// ---------------------------------------------------------------------------
__global__ void __launch_bounds__(N1) iterB_kernel(const float* __restrict__ x)
{
    const int n = blockIdx.x;
    const int k = threadIdx.x;

    const float* pA = (const float*)g_pA4;
    const float* pQ = (const float*)g_pQ4;

    float A = 0.f, q = 0.f;
    #pragma unroll
    for (int c = 0; c < NCH; ++c) {
        A += pA[(c * N2 + n) * N1 + k];
        q += pQ[(c * N2 + n) * N1 + k];
    }
    float s0p = (k < NCH) ? g_pS[k * N2 + n] : 0.f;

    float xp = 0.f;
    for (int i = k; i < D_IN; i += N1) { float v = __ldg(x + i); xp = fmaf(v, v, xp); }

    // fused 5-value reduction: aa, qq, qa, xp, s0
    float aa = A * A, qq = q * q, qa = q * A;
    __shared__ float sm[6][5];
    __shared__ float bc[3];
    #pragma unroll
    for (int o = 16; o > 0; o >>= 1) {
        aa  += __shfl_down_sync(0xffffffffu, aa,  o);
        qq  += __shfl_down_sync(0xffffffffu, qq,  o);
        qa  += __shfl_down_sync(0xffffffffu, qa,  o);
        xp  += __shfl_down_sync(0xffffffffu, xp,  o);
        s0p += __shfl_down_sync(0xffffffffu, s0p, o);
    }
    if ((k & 31) == 0) {
        int w = k >> 5;
        sm[w][0] = aa; sm[w][1] = qq; sm[w][2] = qa; sm[w][3] = xp; sm[w][4] = s0p;
    }
    __syncthreads();

    if (k == 0) {
        float taa = 0.f, tqq = 0.f, tqa = 0.f, txp = 0.f, ts0 = 0.f;
        #pragma unroll
        for (int i = 0; i < 6; ++i) {
            taa += sm[i][0]; tqq += sm[i][1]; tqa += sm[i][2];
            txp += sm[i][3]; ts0 += sm[i][4];
        }
        const float hh    = txp + 1.0f;            // ||h1||^2
        const float invNa = rsqrtf(taa);           // 1/||A_raw||
        const float qA    = tqa * invNa;           // q . Ahat
        const float cc    = 2.0f * LR;

        float p = 0.f, aH = 0.f, beta = 1.0f;
        #pragma unroll 4
        for (int t = 0; t < ITRS; ++t) {
            float qu = p * tqq + aH * qA;                          // q.u
            float uu = p * p * tqq + 2.0f * p * aH * qA + aH * aH; // ||u||^2
            float nw = sqrtf(beta * beta * ts0 + 2.0f * beta * qu + hh * uu);
            float alpha = 1.0f - (LR * LAM) / nw;
            float m = alpha - cc * hh;
            float pn = m * p - cc * beta;
            aH = m * aH + cc;
            p = pn;
            beta *= alpha;
        }
        bc[0] = p;
        bc[1] = aH * invNa;    // coefficient on A_raw
        bc[2] = beta;
        g_beta[n] = beta;
    }
    __syncthreads();

    ((float*)g_u4)[n * N1 + k] = bc[0] * q + bc[1] * A;
}

// ---------------------------------------------------------------------------
// Pass C: W_all = beta_n * W0 + h1 * u^T, float4-vectorized streaming write.
// ---------------------------------------------------------------------------
__global__ void __launch_bounds__(256) outC_kernel(
    const float* __restrict__ x,
    const float* __restrict__ W0,
    float* __restrict__ out)   // points at d_out + 512
{
    const size_t total = (size_t)N2 * D1 * K4;           // 2,361,600 float4s
    size_t idx = (size_t)blockIdx.x * blockDim.x + threadIdx.x;
    if (idx >= total) return;

    int k4 = (int)(idx % K4);
    size_t t = idx / K4;
    int d = (int)(t % D1);
    int n = (int)(t / D1);

    float4 w  = __ldg(((const float4*)W0) + idx);
    float4 uv = g_u4[n * K4 + k4];
    float  h  = (d < D_IN) ? __ldg(x + d) : 1.0f;
    float  b  = g_beta[n];

    float4 o;
    o.x = fmaf(b, w.x, h * uv.x);
    o.y = fmaf(b, w.y, h * uv.y);
    o.z = fmaf(b, w.z, h * uv.z);
    o.w = fmaf(b, w.w, h * uv.w);
    ((float4*)out)[idx] = o;
}

// ---------------------------------------------------------------------------
extern "C" void kernel_launch(void* const* d_in, const int* in_sizes, int n_in,
                              void* d_out, int out_size)
{
    const float* x  = (const float*)d_in[0];
    const float* We = (const float*)d_in[1];
    const float* W0 = (const float*)d_in[2];
    const float* Wp = (const float*)d_in[3];
    const float* bp = (const float*)d_in[4];
    float* out = (float*)d_out;

    // Pass A: stream We + W0 -> partials; pred fused in as extra blocks
    fusedA_kernel<<<NB_RED + NB_PRED, 256>>>(x, We, W0, Wp, bp, out);

    // Pass B: scalar-collapsed GD -> beta, u
    iterB_kernel<<<N2, N1>>>(x);

    // Pass C: write W_all (after the 512 pred floats)
    {
        const size_t total4 = (size_t)N2 * D1 * K4;
        int grid = (int)((total4 + 255) / 256);
        outC_kernel<<<grid, 256>>>(x, W0, out + D_OUT);
    }
}